// round 2
// baseline (speedup 1.0000x reference)
#include <cuda_runtime.h>
#include <math.h>

// ---------------- problem constants ----------------
#define BATCH 32
#define IH 120
#define IW 640
#define C1 256
#define KH1 30
#define KW1 160
#define OH1 91
#define OW1 121
#define C2 256
#define OH2 9
#define OW2 12
#define KTOT2 25600          // 256*10*10
#define NCAP 3456
#define NCLS 5
#define FD 16
#define JD 80                // NCLS*FD
#define NREL 25

// ---------------- device scratch (no runtime allocation allowed) ----------------
__device__ float g_conv1[BATCH * C1 * OH1 * OW1];   // 90,202,112 floats (~361 MB)
__device__ float g_prim[BATCH * C2 * OH2 * OW2];    // 884,736
__device__ float g_up[BATCH * NCAP * JD];           // 8,847,360
__device__ float g_bb[BATCH * NCAP * NCLS];
__device__ float g_cc[BATCH * NCAP * NCLS];
__device__ float g_v[BATCH * NCLS * FD];

// ---------------- packed f32x2 helpers (sm_103a FFMA2) ----------------
__device__ __forceinline__ void fma2(unsigned long long& d, unsigned long long a,
                                     unsigned long long b) {
    asm("fma.rn.f32x2 %0, %1, %2, %0;" : "+l"(d) : "l"(a), "l"(b));
}
__device__ __forceinline__ unsigned long long pack2(float x) {
    unsigned long long r;
    asm("mov.b64 %0, {%1, %1};" : "=l"(r) : "f"(x));
    return r;
}
__device__ __forceinline__ void unpack2(unsigned long long v, float& lo, float& hi) {
    asm("mov.b64 {%0, %1}, %2;" : "=f"(lo), "=f"(hi) : "l"(v));
}

// =====================================================================
// Kernel 1: conv1 + bias + relu.   out (B,256,91,121)
// Block: 256 threads (16x16). Tile: 128 channels x 128 ow (121 used),
// fixed (b, oh). For each kh, ONE 640-float input row feeds the whole
// kw x ow tile. Inner math in packed f32x2 (channel pairs).
// =====================================================================
__global__ __launch_bounds__(256, 2)
void conv1_kernel(const float* __restrict__ in, const float* __restrict__ w,
                  const float* __restrict__ bias, float* __restrict__ out) {
    __shared__ float s_in[672];        // 640 + pad (ow up to 127 reads junk, masked)
    __shared__ float s_w[8][128];      // [kk][channel]

    const int tx = threadIdx.x & 15;   // ow group
    const int ty = threadIdx.x >> 4;   // channel group (8 consecutive channels)
    const int ct = blockIdx.x * 128;   // channel tile base
    const int oh = blockIdx.y;
    const int b  = blockIdx.z;

    unsigned long long acc[4][8];      // [channel pair m][ow j]
#pragma unroll
    for (int m = 0; m < 4; ++m)
#pragma unroll
        for (int j = 0; j < 8; ++j) acc[m][j] = 0ULL;

    const int wc = threadIdx.x >> 1;          // weight-load channel 0..127
    const int wk = (threadIdx.x & 1) * 4;     // weight-load kw sub-offset

    for (int kh = 0; kh < KH1; ++kh) {
        __syncthreads();
        // load input row (b, oh+kh)
        {
            const float4* src = (const float4*)(in + ((size_t)b * IH + oh + kh) * IW);
            for (int idx = threadIdx.x; idx < IW / 4; idx += 256)
                ((float4*)s_in)[idx] = src[idx];
        }
        for (int kw0 = 0; kw0 < KW1; kw0 += 8) {
            if (kw0) __syncthreads();
            // load weights s_w[kk][c] for kk=kw0..kw0+7, c=0..127
            {
                float4 wv = *(const float4*)&w[(size_t)(ct + wc) * (KH1 * KW1) +
                                               kh * KW1 + kw0 + wk];
                s_w[wk + 0][wc] = wv.x;
                s_w[wk + 1][wc] = wv.y;
                s_w[wk + 2][wc] = wv.z;
                s_w[wk + 3][wc] = wv.w;
            }
            __syncthreads();
#pragma unroll
            for (int kk = 0; kk < 8; ++kk) {
                // 8 channels = 4 f32x2 pairs
                ulonglong2 w01 = *(const ulonglong2*)&s_w[kk][ty * 8];
                ulonglong2 w23 = *(const ulonglong2*)&s_w[kk][ty * 8 + 4];
                const int bi = 4 * tx + kw0 + kk;
#pragma unroll
                for (int j = 0; j < 8; ++j) {
                    unsigned long long xp = pack2(s_in[bi + 64 * j]);
                    fma2(acc[0][j], w01.x, xp);
                    fma2(acc[1][j], w01.y, xp);
                    fma2(acc[2][j], w23.x, xp);
                    fma2(acc[3][j], w23.y, xp);
                }
            }
        }
    }

    // epilogue: bias + relu + store
#pragma unroll
    for (int m = 0; m < 4; ++m) {
        const int c0 = ct + ty * 8 + 2 * m;
        const float b0 = bias[c0], b1 = bias[c0 + 1];
        float* o0 = out + ((size_t)(b * C1 + c0) * OH1 + oh) * OW1;
        float* o1 = o0 + (size_t)OH1 * OW1;
#pragma unroll
        for (int j = 0; j < 8; ++j) {
            const int ow = tx + 16 * j;
            if (ow < OW1) {
                float lo, hi;
                unpack2(acc[m][j], lo, hi);
                o0[ow] = fmaxf(lo + b0, 0.0f);
                o1[ow] = fmaxf(hi + b1, 0.0f);
            }
        }
    }
}

// =====================================================================
// Kernel 2: conv2 (prim caps) + bias (NO relu).  out (B,256,9,12)
// GEMM: M=256 (c2) x N=108 (per-b positions) x K=25600.
// Block: fixed b, 64-channel tile. 256 threads (16x16), thread 4c2 x 7n.
// =====================================================================
__global__ __launch_bounds__(256)
void conv2_kernel(const float* __restrict__ relu1, const float* __restrict__ w2,
                  const float* __restrict__ pb, float* __restrict__ out) {
    __shared__ float s_w[16][64];
    __shared__ float s_b[16][112];

    const int tx = threadIdx.x & 15;
    const int ty = threadIdx.x >> 4;
    const int cb = blockIdx.x * 64;
    const int b  = blockIdx.y;

    float acc[4][7];
#pragma unroll
    for (int m = 0; m < 4; ++m)
#pragma unroll
        for (int j = 0; j < 7; ++j) acc[m][j] = 0.0f;

    const int wc = threadIdx.x >> 2;        // 0..63
    const int wk = (threadIdx.x & 3) * 4;   // 0,4,8,12
    const float* r1b = relu1 + (size_t)b * C1 * OH1 * OW1;

    for (int k0 = 0; k0 < KTOT2; k0 += 16) {
        __syncthreads();
        {   // weight tile
            float4 wv = *(const float4*)&w2[(size_t)(cb + wc) * KTOT2 + k0 + wk];
            s_w[wk + 0][wc] = wv.x;
            s_w[wk + 1][wc] = wv.y;
            s_w[wk + 2][wc] = wv.z;
            s_w[wk + 3][wc] = wv.w;
        }
        // B tile (im2col gather)
        for (int idx = threadIdx.x; idx < 16 * 112; idx += 256) {
            const int kk = idx / 112;
            const int nl = idx - kk * 112;
            float v = 0.0f;
            if (nl < 108) {
                const int k = k0 + kk;
                const int c1 = k / 100;
                const int r  = k - c1 * 100;
                const int kh = r / 10;
                const int kw = r - kh * 10;
                const int ohh = nl / 12;
                const int oww = nl - ohh * 12;
                v = r1b[((size_t)c1 * OH1 + ohh * 10 + kh) * OW1 + oww * 10 + kw];
            }
            s_b[kk][nl] = v;
        }
        __syncthreads();
#pragma unroll
        for (int kk = 0; kk < 16; ++kk) {
            float4 wv = *(const float4*)&s_w[kk][ty * 4];
            float xr[7];
#pragma unroll
            for (int j = 0; j < 7; ++j) xr[j] = s_b[kk][tx + 16 * j];
#pragma unroll
            for (int j = 0; j < 7; ++j) {
                acc[0][j] += wv.x * xr[j];
                acc[1][j] += wv.y * xr[j];
                acc[2][j] += wv.z * xr[j];
                acc[3][j] += wv.w * xr[j];
            }
        }
    }

#pragma unroll
    for (int m = 0; m < 4; ++m) {
        const int c2 = cb + ty * 4 + m;
        const float bb = pb[c2];
#pragma unroll
        for (int j = 0; j < 7; ++j) {
            const int nl = tx + 16 * j;
            if (nl < 108)
                out[((size_t)b * C2 + c2) * 108 + nl] = acc[m][j] + bb;
        }
    }
}

// =====================================================================
// Kernel 3: primary-caps squash + caps prediction (8 -> 80 per capsule)
// grid (NCAP, B), block 80: thread j computes up[b,i,j].
// capsule i = g*108 + p ; its 8 dims are channels g*8..g*8+7 at position p.
// =====================================================================
__global__ void squash_predict_kernel(const float* __restrict__ prim,
                                      const float* __restrict__ caps_w,
                                      float* __restrict__ up) {
    __shared__ float su[8];
    __shared__ float sfac;
    const int i = blockIdx.x;
    const int b = blockIdx.y;
    const int g = i / 108;
    const int p = i - g * 108;
    const int t = threadIdx.x;

    if (t < 8) su[t] = prim[((size_t)b * C2 + g * 8 + t) * 108 + p];
    __syncthreads();
    if (t == 0) {
        float l2 = 0.0f;
#pragma unroll
        for (int d = 0; d < 8; ++d) l2 += su[d] * su[d];
        sfac = sqrtf(l2) / (1.0f + l2);
    }
    __syncthreads();
    const float f = sfac;
    const float* cw = caps_w + (size_t)i * 8 * JD + t;
    float a = 0.0f;
#pragma unroll
    for (int d = 0; d < 8; ++d) a += su[d] * f * cw[d * JD];
    up[((size_t)b * NCAP + i) * JD + t] = a;
}

// =====================================================================
// Routing: s = sum_i c*up ; v = squash(s).  grid (NCLS, B), 256 threads.
// mode 0: c = softmax(b_route) (iteration 0);  mode 1: c from g_cc.
// =====================================================================
__global__ void route_s_kernel(const float* __restrict__ up,
                               const float* __restrict__ b_route,
                               const float* __restrict__ cmat,
                               float* __restrict__ vout, int mode) {
    const int o = blockIdx.x;
    const int b = blockIdx.y;
    const int t = threadIdx.x;
    const int lane = t & 31, wid = t >> 5;

    float sd[FD];
#pragma unroll
    for (int d = 0; d < FD; ++d) sd[d] = 0.0f;

    for (int i = t; i < NCAP; i += 256) {
        float ci;
        if (mode == 0) {
            float br[NCLS];
#pragma unroll
            for (int oo = 0; oo < NCLS; ++oo) br[oo] = b_route[i * NCLS + oo];
            float m = br[0];
#pragma unroll
            for (int oo = 1; oo < NCLS; ++oo) m = fmaxf(m, br[oo]);
            float s = 0.0f;
#pragma unroll
            for (int oo = 0; oo < NCLS; ++oo) s += expf(br[oo] - m);
            ci = expf(br[o] - m) / s;
        } else {
            ci = cmat[((size_t)b * NCAP + i) * NCLS + o];
        }
        const float* u = up + ((size_t)b * NCAP + i) * JD + o * FD;
#pragma unroll
        for (int d = 0; d < FD; ++d) sd[d] += ci * u[d];
    }
#pragma unroll
    for (int d = 0; d < FD; ++d)
        for (int off = 16; off; off >>= 1)
            sd[d] += __shfl_down_sync(0xffffffffu, sd[d], off);

    __shared__ float part[8][FD];
    __shared__ float fin[FD];
    __shared__ float fac;
    if (lane == 0)
#pragma unroll
        for (int d = 0; d < FD; ++d) part[wid][d] = sd[d];
    __syncthreads();
    if (t < FD) {
        float tot = 0.0f;
#pragma unroll
        for (int ww = 0; ww < 8; ++ww) tot += part[ww][t];
        fin[t] = tot;
    }
    __syncthreads();
    if (t == 0) {
        float l2 = 0.0f;
#pragma unroll
        for (int d = 0; d < FD; ++d) l2 += fin[d] * fin[d];
        fac = sqrtf(l2) / (1.0f + l2);
    }
    __syncthreads();
    if (t < FD) vout[((size_t)b * NCLS + o) * FD + t] = fin[t] * fac;
}

// =====================================================================
// Routing: b_batch += up.v ; c = softmax(b_batch).  one thread per (b,i)
// =====================================================================
__global__ void route_b_kernel(const float* __restrict__ up,
                               const float* __restrict__ b_route,
                               const float* __restrict__ v,
                               float* __restrict__ bb,
                               float* __restrict__ cmat, int first) {
    const int gid = blockIdx.x * blockDim.x + threadIdx.x;
    if (gid >= BATCH * NCAP) return;
    const int b = gid / NCAP;
    const int i = gid - b * NCAP;
    const float* u  = up + (size_t)gid * JD;
    const float* vb = v + (size_t)b * JD;

    float lg[NCLS];
#pragma unroll
    for (int o = 0; o < NCLS; ++o) {
        float dot = 0.0f;
#pragma unroll
        for (int d = 0; d < FD; ++d) dot += u[o * FD + d] * vb[o * FD + d];
        const float prev = first ? b_route[i * NCLS + o] : bb[(size_t)gid * NCLS + o];
        lg[o] = prev + dot;
        bb[(size_t)gid * NCLS + o] = lg[o];
    }
    float m = lg[0];
#pragma unroll
    for (int o = 1; o < NCLS; ++o) m = fmaxf(m, lg[o]);
    float s = 0.0f;
#pragma unroll
    for (int o = 0; o < NCLS; ++o) { lg[o] = expf(lg[o] - m); s += lg[o]; }
    const float inv = 1.0f / s;
#pragma unroll
    for (int o = 0; o < NCLS; ++o) cmat[(size_t)gid * NCLS + o] = lg[o] * inv;
}

// =====================================================================
// Heads: logits + log_softmax.  1 block, thread per (b,o).
// =====================================================================
__global__ void head_kernel(const float* __restrict__ v,
                            const float* __restrict__ pred_w,
                            const float* __restrict__ pred_b,
                            const float* __restrict__ eos_w,
                            const float* __restrict__ eos_b,
                            float* __restrict__ out) {
    const int t = threadIdx.x;
    if (t >= BATCH * NCLS) return;
    const float* vv = v + (size_t)t * FD;
    float lg[NREL + 1];
#pragma unroll 4
    for (int r = 0; r < NREL; ++r) {
        float a = pred_b[r];
#pragma unroll
        for (int d = 0; d < FD; ++d) a += vv[d] * pred_w[r * FD + d];
        lg[r] = a;
    }
    {
        float a = eos_b[0];
#pragma unroll
        for (int d = 0; d < FD; ++d) a += vv[d] * eos_w[d];
        lg[NREL] = a;
    }
    float m = lg[0];
#pragma unroll
    for (int k = 1; k <= NREL; ++k) m = fmaxf(m, lg[k]);
    float s = 0.0f;
#pragma unroll
    for (int k = 0; k <= NREL; ++k) s += expf(lg[k] - m);
    const float ls = m + logf(s);
#pragma unroll
    for (int k = 0; k <= NREL; ++k) out[(size_t)t * (NREL + 1) + k] = lg[k] - ls;
}

// =====================================================================
extern "C" void kernel_launch(void* const* d_in, const int* in_sizes, int n_in,
                              void* d_out, int out_size) {
    const float* input   = (const float*)d_in[0];
    const float* conv1_w = (const float*)d_in[1];
    const float* conv1_b = (const float*)d_in[2];
    const float* prim_w  = (const float*)d_in[3];
    const float* prim_b  = (const float*)d_in[4];
    const float* caps_w  = (const float*)d_in[5];
    const float* b_route = (const float*)d_in[6];
    const float* pred_w  = (const float*)d_in[7];
    const float* pred_b  = (const float*)d_in[8];
    const float* eos_w   = (const float*)d_in[9];
    const float* eos_b   = (const float*)d_in[10];
    float* out = (float*)d_out;

    float *conv1p, *primp, *upp, *bbp, *ccp, *vp;
    cudaGetSymbolAddress((void**)&conv1p, g_conv1);
    cudaGetSymbolAddress((void**)&primp, g_prim);
    cudaGetSymbolAddress((void**)&upp, g_up);
    cudaGetSymbolAddress((void**)&bbp, g_bb);
    cudaGetSymbolAddress((void**)&ccp, g_cc);
    cudaGetSymbolAddress((void**)&vp, g_v);

    // conv1 + relu
    conv1_kernel<<<dim3(2, OH1, BATCH), 256>>>(input, conv1_w, conv1_b, conv1p);
    // conv2 (prim caps)
    conv2_kernel<<<dim3(4, BATCH), 256>>>(conv1p, prim_w, prim_b, primp);
    // squash + caps prediction
    squash_predict_kernel<<<dim3(NCAP, BATCH), 80>>>(primp, caps_w, upp);
    // routing iteration 0 (uniform c from b_route)
    route_s_kernel<<<dim3(NCLS, BATCH), 256>>>(upp, b_route, ccp, vp, 0);
    for (int it = 0; it < 3; ++it) {
        route_b_kernel<<<(BATCH * NCAP + 255) / 256, 256>>>(upp, b_route, vp, bbp,
                                                            ccp, it == 0 ? 1 : 0);
        route_s_kernel<<<dim3(NCLS, BATCH), 256>>>(upp, b_route, ccp, vp, 1);
    }
    // heads + log_softmax
    head_kernel<<<1, BATCH * NCLS>>>(vp, pred_w, pred_b, eos_w, eos_b, out);
}